// round 9
// baseline (speedup 1.0000x reference)
#include <cuda_runtime.h>
#include <cuda_bf16.h>
#include <cstdint>
#include <math.h>

#define IN_DIM 128
#define HID    32
#define NCLS   30
#define CP     32            // padded row width (128B fp32 rows)
#define NMAX   100000
#define EMAX   3200000
#define EPAD   4001024       // >= EMAX + 8*(NMAX+1)
#define G2MAX  2048          // gather2 grid size (fixed)
#define FFMAX  1024          // ff grid size (fixed)
#define REG_C  0.01

// ---------------- static scratch ----------------
__device__ float  d_g1 [(NMAX + 1) * CP];   // g1 rows + zero sentinel row N
__device__ float  d_g2 [(NMAX + 1) * CP];   // g2 rows + zero sentinel row N
__device__ __nv_bfloat162 d_fx16[(NMAX + 1) * 16];  // FX bf16 rows + zero row N
__device__ int    d_cnt [NMAX + 1];
__device__ int    d_cur [NMAX + 1];
__device__ int    d_rp  [NMAX + 1];         // padded CSR row pointers (mult of 8)
__device__ int    d_src32[EMAX];
__device__ int    d_dst32[EMAX];
__device__ int2   d_csr2[EPAD];             // (src, ep_bits) grouped by dst
__device__ float  d_dinv[NMAX];
__device__ int    d_blocksum[1024];
__device__ float  d_partialS[32 * G2MAX];
__device__ float  d_partialM[FFMAX];
__device__ int    d_is64;

__device__ __forceinline__ float ldcg_f(const float* p) {
    float v;
    asm volatile("ld.global.cg.f32 %0, [%1];" : "=f"(v) : "l"(p));
    return v;
}

// ---------------- init: cnt=0, zero sentinel rows, dtype detect ------------
__global__ void init_k(const unsigned int* __restrict__ w, int N) {
    int i = blockIdx.x * blockDim.x + threadIdx.x;
    if (i <= N) d_cnt[i] = 0;
    if (i < CP) {
        d_g1[(size_t)N * CP + i] = 0.f;
        d_g2[(size_t)N * CP + i] = 0.f;
        if (i < 16) d_fx16[(size_t)N * 16 + i] = __nv_bfloat162(__nv_bfloat16(0.f), __nv_bfloat16(0.f));
    }
    if (blockIdx.x == 0 && threadIdx.x < 64) {
        unsigned int v = w[2 * threadIdx.x + 1];
        unsigned int any = __ballot_sync(0xffffffffu, v != 0);
        if (threadIdx.x == 0) d_is64 = (any == 0) ? 1 : 0;
    }
}

// ---------------- count + int32 conversion --------------------------------
__global__ void count_convert(const void* __restrict__ ei, int E) {
    int e = blockIdx.x * blockDim.x + threadIdx.x;
    if (e >= E) return;
    int s, d;
    if (d_is64) {
        const long long* p = (const long long*)ei;
        s = (int)p[e]; d = (int)p[(size_t)E + e];
    } else {
        const int* p = (const int*)ei;
        s = p[e]; d = p[(size_t)E + e];
    }
    d_src32[e] = s; d_dst32[e] = d;
    atomicAdd(&d_cnt[d], 1);
}

// ---------------- scan over PADDED counts (N+1 elements) + dinv ------------
__global__ void scan1(int N) {
    __shared__ int sh[1024];
    int gid = blockIdx.x * 1024 + threadIdx.x;
    int cnt = 0, v = 0;
    if (gid <= N) { cnt = d_cnt[gid]; v = (cnt + 7) & ~7; }
    if (gid < N) d_dinv[gid] = rsqrtf((float)(cnt + 1));    // fused dinv
    sh[threadIdx.x] = v; __syncthreads();
    for (int off = 1; off < 1024; off <<= 1) {
        int t = (threadIdx.x >= off) ? sh[threadIdx.x - off] : 0;
        __syncthreads();
        sh[threadIdx.x] += t;
        __syncthreads();
    }
    int incl = sh[threadIdx.x];
    if (gid <= N) d_cur[gid] = incl - v;          // block-local exclusive
    if (threadIdx.x == 1023) d_blocksum[blockIdx.x] = incl;
}

// scan3 with inlined block-offset computation
__global__ void scan3(int N) {
    __shared__ int off_sh;
    int lane = threadIdx.x & 31;
    if (threadIdx.x < 32) {
        int s = 0;
        for (int k = lane; k < blockIdx.x; k += 32) s += d_blocksum[k];
#pragma unroll
        for (int o = 16; o; o >>= 1) s += __shfl_down_sync(0xffffffffu, s, o);
        if (lane == 0) off_sh = s;
    }
    __syncthreads();
    int gid = blockIdx.x * 1024 + threadIdx.x;
    if (gid <= N) {
        int rp = d_cur[gid] + off_sh;
        d_rp[gid] = rp;
        d_cur[gid] = rp;                           // fill cursor
    }
}

// ---------------- pad tails with sentinel (disjoint from fill slots) -------
__global__ void pad_k(int N) {
    int v = blockIdx.x * blockDim.x + threadIdx.x;
    if (v >= N) return;
    int start = d_rp[v] + d_cnt[v];
    int end   = d_rp[v + 1];
    for (int p = start; p < end; p++) d_csr2[p] = make_int2(N, 0);
}

// ---------------- CSR fill: (src, ep_bits) ---------------------------------
__global__ void fill_k(const float* __restrict__ ep, int E) {
    int e = blockIdx.x * blockDim.x + threadIdx.x;
    if (e >= E) return;
    int d = d_dst32[e];
    int pos = atomicAdd(&d_cur[d], 1);
    d_csr2[pos] = make_int2(d_src32[e], __float_as_int(ep[e]));
}

// ---------------- GEMM1 (raw): g1 = x @ W1 (aux stream) --------------------
__global__ void gemm1_raw(const float* __restrict__ x, const float* __restrict__ W1, int N) {
    __shared__ float Ws[IN_DIM * HID];
    for (int i = threadIdx.x; i < IN_DIM * HID; i += blockDim.x) Ws[i] = W1[i];
    __syncthreads();
    int r = blockIdx.x * blockDim.x + threadIdx.x;
    if (r >= N) return;

    float acc[HID];
#pragma unroll
    for (int c = 0; c < HID; c++) acc[c] = 0.f;

    const float4* x4 = reinterpret_cast<const float4*>(x + (size_t)r * IN_DIM);
#pragma unroll 4
    for (int k4 = 0; k4 < IN_DIM / 4; k4++) {
        float4 xv = x4[k4];
        int k = k4 * 4;
#pragma unroll
        for (int c = 0; c < HID; c++) {
            acc[c] += xv.x * Ws[(k + 0) * HID + c]
                    + xv.y * Ws[(k + 1) * HID + c]
                    + xv.z * Ws[(k + 2) * HID + c]
                    + xv.w * Ws[(k + 3) * HID + c];
        }
    }
    float* out = d_g1 + (size_t)r * CP;
#pragma unroll
    for (int c = 0; c < HID; c++) out[c] = acc[c];
}

// ---------------- scale g1 by dinv (join point) ----------------------------
__global__ void scaleg1(int N) {
    int i = blockIdx.x * blockDim.x + threadIdx.x;
    int n4 = N * CP / 4;
    if (i >= n4) return;
    float s = d_dinv[i >> 3];
    float4* p = reinterpret_cast<float4*>(d_g1) + i;
    float4 v = *p;
    v.x *= s; v.y *= s; v.z *= s; v.w *= s;
    *p = v;
}

// ---- gather layer1 (8-wide, sentinel-padded) fused with GEMM2 -------------
__global__ void gather1(const float* __restrict__ b1, const float* __restrict__ W2, int N) {
    __shared__ float Ws[HID * CP];
    for (int i = threadIdx.x; i < HID * CP; i += blockDim.x) {
        int k = i / CP, c = i % CP;
        Ws[i] = (c < NCLS) ? W2[k * NCLS + c] : 0.f;
    }
    __syncthreads();

    int tid  = threadIdx.x;
    int lane = tid & 31;
    int warp = (blockIdx.x * blockDim.x + tid) >> 5;
    int nwarps = (gridDim.x * blockDim.x) >> 5;
    float bv = b1[lane];

    for (int v = warp; v < N; v += nwarps) {
        int beg = d_rp[v];
        int nb  = (d_rp[v + 1] - beg) >> 3;          // blocks of 8 entries
        const int4* ip = reinterpret_cast<const int4*>(d_csr2 + beg);  // 2 entries/int4
        float acc = 0.f;
        int4 q0, q1, q2, q3;
        if (nb > 0) { q0 = ip[0]; q1 = ip[1]; q2 = ip[2]; q3 = ip[3]; }
        for (int b = 0; b < nb; b++) {
            int4 n0, n1, n2, n3;
            if (b + 1 < nb) {
                n0 = ip[4 * b + 4]; n1 = ip[4 * b + 5];
                n2 = ip[4 * b + 6]; n3 = ip[4 * b + 7];
            }
            float a0 = ldcg_f(d_g1 + (size_t)q0.x * CP + lane);
            float a1 = ldcg_f(d_g1 + (size_t)q0.z * CP + lane);
            float a2 = ldcg_f(d_g1 + (size_t)q1.x * CP + lane);
            float a3 = ldcg_f(d_g1 + (size_t)q1.z * CP + lane);
            float a4 = ldcg_f(d_g1 + (size_t)q2.x * CP + lane);
            float a5 = ldcg_f(d_g1 + (size_t)q2.z * CP + lane);
            float a6 = ldcg_f(d_g1 + (size_t)q3.x * CP + lane);
            float a7 = ldcg_f(d_g1 + (size_t)q3.z * CP + lane);
            acc += ((a0 + a1) + (a2 + a3)) + ((a4 + a5) + (a6 + a7));
            q0 = n0; q1 = n1; q2 = n2; q3 = n3;
        }
        float dv = d_dinv[v];
        float h = fmaxf(dv * (acc + d_g1[(size_t)v * CP + lane]) + bv, 0.f);

        // fused GEMM2: g2[c] = dv * sum_k h[k] * W2[k][c]
        float g2c = 0.f;
#pragma unroll
        for (int k = 0; k < HID; k++) {
            float hk = __shfl_sync(0xffffffffu, h, k);
            g2c += hk * Ws[k * CP + lane];
        }
        d_g2[(size_t)v * CP + lane] = dv * g2c;
    }
}

// ---- gather layer2 (8-wide) + softmax + FX + bf16 copy + NFX partials -----
__global__ void gather2(const float* __restrict__ b2, float* __restrict__ fx_out, int N) {
    __shared__ float Ss[32];
    int tid  = threadIdx.x;
    int lane = tid & 31;
    if (tid < 32) Ss[tid] = 0.f;
    __syncthreads();

    int warp = (blockIdx.x * blockDim.x + tid) >> 5;
    int nwarps = (gridDim.x * blockDim.x) >> 5;
    float bv = (lane < NCLS) ? b2[lane] : 0.f;
    float ls = 0.f;

    for (int v = warp; v < N; v += nwarps) {
        int beg = d_rp[v];
        int nb  = (d_rp[v + 1] - beg) >> 3;
        const int4* ip = reinterpret_cast<const int4*>(d_csr2 + beg);
        float acc = 0.f;
        int4 q0, q1, q2, q3;
        if (nb > 0) { q0 = ip[0]; q1 = ip[1]; q2 = ip[2]; q3 = ip[3]; }
        for (int b = 0; b < nb; b++) {
            int4 n0, n1, n2, n3;
            if (b + 1 < nb) {
                n0 = ip[4 * b + 4]; n1 = ip[4 * b + 5];
                n2 = ip[4 * b + 6]; n3 = ip[4 * b + 7];
            }
            float a0 = ldcg_f(d_g2 + (size_t)q0.x * CP + lane);
            float a1 = ldcg_f(d_g2 + (size_t)q0.z * CP + lane);
            float a2 = ldcg_f(d_g2 + (size_t)q1.x * CP + lane);
            float a3 = ldcg_f(d_g2 + (size_t)q1.z * CP + lane);
            float a4 = ldcg_f(d_g2 + (size_t)q2.x * CP + lane);
            float a5 = ldcg_f(d_g2 + (size_t)q2.z * CP + lane);
            float a6 = ldcg_f(d_g2 + (size_t)q3.x * CP + lane);
            float a7 = ldcg_f(d_g2 + (size_t)q3.z * CP + lane);
            acc += ((a0 + a1) + (a2 + a3)) + ((a4 + a5) + (a6 + a7));
            q0 = n0; q1 = n1; q2 = n2; q3 = n3;
        }
        float logit = d_dinv[v] * (acc + d_g2[(size_t)v * CP + lane]) + bv;
        if (lane >= NCLS) logit = -1e30f;

        float mx = logit;
#pragma unroll
        for (int o = 16; o; o >>= 1) mx = fmaxf(mx, __shfl_xor_sync(0xffffffffu, mx, o));
        float ex = expf(logit - mx);
        float sum = ex;
#pragma unroll
        for (int o = 16; o; o >>= 1) sum += __shfl_xor_sync(0xffffffffu, sum, o);
        float fx = ex / sum;                       // 0 for lane>=NCLS

        float fx_hi = __shfl_down_sync(0xffffffffu, fx, 1);
        if ((lane & 1) == 0)
            d_fx16[(size_t)v * 16 + (lane >> 1)] = __floats2bfloat162_rn(fx, fx_hi);

        if (lane < NCLS) {
            fx_out[(size_t)v * NCLS + lane] = fx;
            ls += log1pf(-fx * fx);
        }
    }
    atomicAdd(&Ss[lane], ls);
    __syncthreads();
    if (tid < NCLS) d_partialS[tid * gridDim.x + blockIdx.x] = Ss[tid];
}

// ---------------- FF + MSE via CSR walk (warp/node, 4 nbrs/iter) -----------
__global__ void ff_k(int N) {
    __shared__ float sAcc;
    int tid  = threadIdx.x;
    int lane = tid & 31;
    if (tid == 0) sAcc = 0.f;
    __syncthreads();

    int warp = (blockIdx.x * blockDim.x + tid) >> 5;
    int nwarps = (gridDim.x * blockDim.x) >> 5;
    int sub = lane & 7;          // position in 8-lane group
    int grp = lane >> 3;         // group 0..3
    float acc = 0.f;

    for (int v = warp; v < N; v += nwarps) {
        const uint2* rowv = reinterpret_cast<const uint2*>(d_fx16 + (size_t)v * 16);
        uint2 fv = rowv[sub];                     // FX[v] row, replicated per group
        int beg = d_rp[v];
        int nb  = (d_rp[v + 1] - beg) >> 3;       // blocks of 8 entries
        for (int b = 0; b < nb; b++) {
#pragma unroll
            for (int j = 0; j < 2; j++) {
                int2 ent = d_csr2[beg + b * 8 + j * 4 + grp];
                const uint2* rows = reinterpret_cast<const uint2*>(d_fx16 + (size_t)ent.x * 16);
                uint2 rv = rows[sub];
                float2 a0 = __bfloat1622float2(*reinterpret_cast<const __nv_bfloat162*>(&fv.x));
                float2 a1 = __bfloat1622float2(*reinterpret_cast<const __nv_bfloat162*>(&fv.y));
                float2 b0 = __bfloat1622float2(*reinterpret_cast<const __nv_bfloat162*>(&rv.x));
                float2 b1 = __bfloat1622float2(*reinterpret_cast<const __nv_bfloat162*>(&rv.y));
                float p = a0.x * b0.x + a0.y * b0.y + a1.x * b1.x + a1.y * b1.y;
                p += __shfl_down_sync(0xffffffffu, p, 4);
                p += __shfl_down_sync(0xffffffffu, p, 2);
                p += __shfl_down_sync(0xffffffffu, p, 1);
                if (sub == 0) {
                    float diff = p - __int_as_float(ent.y);   // pads: 0-0=0
                    acc += diff * diff;
                }
            }
        }
    }
    // leaders at lanes 0,8,16,24 hold acc; others are 0
    acc += __shfl_down_sync(0xffffffffu, acc, 16);
    acc += __shfl_down_sync(0xffffffffu, acc, 8);
    if (lane == 0) atomicAdd(&sAcc, acc);
    __syncthreads();
    if (tid == 0) d_partialM[blockIdx.x] = sAcc;
}

// ---------------- finalize loss -------------------------------------------
__global__ void fin_k(float* __restrict__ out, int N, int E, int out_size) {
    __shared__ double sS[32];
    __shared__ double red[32];
    int tid = threadIdx.x, w = tid >> 5, lane = tid & 31;

    if (w < NCLS) {
        float s = 0.f;
        for (int k = lane; k < G2MAX; k += 32) s += d_partialS[w * G2MAX + k];
#pragma unroll
        for (int o = 16; o; o >>= 1) s += __shfl_down_sync(0xffffffffu, s, o);
        if (lane == 0) sS[w] = (double)s;
    }

    double m = 0.0;
    for (int k = tid; k < FFMAX; k += 1024) m += (double)d_partialM[k];
#pragma unroll
    for (int o = 16; o; o >>= 1) m += __shfl_down_sync(0xffffffffu, m, o);
    if (lane == 0) red[w] = m;
    __syncthreads();

    if (tid == 0) {
        double mm = 0.0;
        for (int i = 0; i < 32; i++) mm += red[i];
        double preg = 0.0;
        for (int c = 0; c < NCLS; c++)
            preg -= log(1.0001 - exp(sS[c]));
        double loss = mm / (double)E + REG_C * preg;
        if (out_size > N * NCLS) out[(size_t)N * NCLS] = (float)loss;
    }
}

// ---------------- launch ---------------------------------------------------
extern "C" void kernel_launch(void* const* d_in, const int* in_sizes, int n_in,
                              void* d_out, int out_size) {
    const float* x   = (const float*)d_in[0];
    const void*  ei  = d_in[1];
    const float* ep  = (const float*)d_in[2];
    const float* W1  = (const float*)d_in[3];
    const float* b1  = (const float*)d_in[4];
    const float* W2  = (const float*)d_in[5];
    const float* b2  = (const float*)d_in[6];
    float* out = (float*)d_out;

    int N = in_sizes[0] / IN_DIM;    // 100000
    int E = in_sizes[2];             // 3200000
    int nb_scan = (N + 1 + 1023) / 1024;
    int n4 = N * CP / 4;

    static cudaStream_t s_aux = nullptr;
    static cudaEvent_t ev_root = nullptr, ev_scan1 = nullptr, ev_g1 = nullptr;
    if (s_aux == nullptr) {
        cudaStreamCreateWithFlags(&s_aux, cudaStreamNonBlocking);
        cudaEventCreateWithFlags(&ev_root, cudaEventDisableTiming);
        cudaEventCreateWithFlags(&ev_scan1, cudaEventDisableTiming);
        cudaEventCreateWithFlags(&ev_g1,   cudaEventDisableTiming);
    }

    const int T = 256;

    // fork: aux stream runs gemm1_raw concurrently with CSR build
    cudaEventRecord(ev_root, 0);
    cudaStreamWaitEvent(s_aux, ev_root, 0);
    gemm1_raw<<<(N + 127) / 128, 128, 0, s_aux>>>(x, W1, N);          // launch 1

    // main chain
    init_k       <<<(N + 1 + T - 1) / T, T>>>((const unsigned int*)ei, N); // 2
    count_convert<<<(E + T - 1) / T, T>>>(ei, E);                     // 3
    // profiling probe: same gather1 code on prior-replay state (N/4 nodes).
    // Output (d_g2 rows [0,N/4)) is fully overwritten by the real gather1.
    gather1      <<<512, 256>>>(b1, W2, N / 4);                       // 4 <- ncu slot
    scan1        <<<nb_scan, 1024>>>(N);                              // 5
    cudaEventRecord(ev_scan1, 0);

    cudaStreamWaitEvent(s_aux, ev_scan1, 0);
    scaleg1<<<(n4 + T - 1) / T, T, 0, s_aux>>>(N);                    // 6
    cudaEventRecord(ev_g1, s_aux);

    scan3        <<<nb_scan, 1024>>>(N);                              // 7
    pad_k        <<<(N + T - 1) / T, T>>>(N);                         // 8
    fill_k       <<<(E + T - 1) / T, T>>>(ep, E);                     // 9

    cudaStreamWaitEvent(0, ev_g1, 0);
    gather1      <<<2048, 256>>>(b1, W2, N);                          // 10
    gather2      <<<G2MAX, 256>>>(b2, out, N);                        // 11
    ff_k         <<<FFMAX, 256>>>(N);                                 // 12
    fin_k        <<<1, 1024>>>(out, N, E, out_size);                  // 13
}

// round 13
// speedup vs baseline: 1.2824x; 1.2824x over previous
#include <cuda_runtime.h>
#include <cuda_bf16.h>
#include <cstdint>
#include <math.h>

#define IN_DIM 128
#define HID    32
#define NCLS   30
#define CP     32            // padded row width (128B fp32 rows)
#define NMAX   100000
#define EMAX   3200000
#define EPAD   4001024       // >= EMAX + 8*(NMAX+1)
#define G2MAX  2048          // gather2 grid size (fixed)
#define PARTM  32768
#define REG_C  0.01

// ---------------- static scratch ----------------
__device__ float  d_g1 [(NMAX + 1) * CP];   // g1 rows + zero sentinel row N
__device__ float  d_g2 [(NMAX + 1) * CP];   // g2 rows + zero sentinel row N
__device__ __nv_bfloat162 d_fx16[NMAX * 16];
__device__ int    d_cnt [NMAX + 1];
__device__ int    d_cur [NMAX + 1];
__device__ int    d_rp  [NMAX + 1];         // padded CSR row pointers (mult of 8)
__device__ int    d_src32[EMAX];
__device__ int    d_dst32[EMAX];
__device__ int    d_csr [EPAD];
__device__ float  d_dinv[NMAX];
__device__ int    d_blocksum[1024];
__device__ float  d_partialS[32 * G2MAX];
__device__ float  d_partialM[PARTM];
__device__ int    d_is64;

// ---------------- init: cnt=0, zero sentinel rows, dtype detect ------------
__global__ void init_k(const unsigned int* __restrict__ w, int N) {
    int i = blockIdx.x * blockDim.x + threadIdx.x;
    if (i <= N) d_cnt[i] = 0;
    if (i < CP) {
        d_g1[(size_t)N * CP + i] = 0.f;
        d_g2[(size_t)N * CP + i] = 0.f;
    }
    if (blockIdx.x == 0 && threadIdx.x < 64) {
        unsigned int v = w[2 * threadIdx.x + 1];
        unsigned int any = __ballot_sync(0xffffffffu, v != 0);
        if (threadIdx.x == 0) d_is64 = (any == 0) ? 1 : 0;
    }
}

// ---------------- count + int32 conversion --------------------------------
__global__ void count_convert(const void* __restrict__ ei, int E) {
    int e = blockIdx.x * blockDim.x + threadIdx.x;
    if (e >= E) return;
    int s, d;
    if (d_is64) {
        const long long* p = (const long long*)ei;
        s = (int)p[e]; d = (int)p[(size_t)E + e];
    } else {
        const int* p = (const int*)ei;
        s = p[e]; d = p[(size_t)E + e];
    }
    d_src32[e] = s; d_dst32[e] = d;
    atomicAdd(&d_cnt[d], 1);
}

// ---------------- scan over PADDED counts (N+1 elements) + fused dinv ------
__global__ void scan1(int N) {
    __shared__ int sh[1024];
    int gid = blockIdx.x * 1024 + threadIdx.x;
    int cnt = 0, v = 0;
    if (gid <= N) { cnt = d_cnt[gid]; v = (cnt + 7) & ~7; }
    if (gid < N) d_dinv[gid] = rsqrtf((float)(cnt + 1));    // +1 self loop
    sh[threadIdx.x] = v; __syncthreads();
    for (int off = 1; off < 1024; off <<= 1) {
        int t = (threadIdx.x >= off) ? sh[threadIdx.x - off] : 0;
        __syncthreads();
        sh[threadIdx.x] += t;
        __syncthreads();
    }
    int incl = sh[threadIdx.x];
    if (gid <= N) d_cur[gid] = incl - v;          // block-local exclusive
    if (threadIdx.x == 1023) d_blocksum[blockIdx.x] = incl;
}

// scan3: inlined block offsets + rp/cursor write + sentinel tail padding
__global__ void scan3(int N) {
    __shared__ int off_sh;
    int lane = threadIdx.x & 31;
    if (threadIdx.x < 32) {
        int s = 0;
        for (int k = lane; k < blockIdx.x; k += 32) s += d_blocksum[k];
#pragma unroll
        for (int o = 16; o; o >>= 1) s += __shfl_down_sync(0xffffffffu, s, o);
        if (lane == 0) off_sh = s;
    }
    __syncthreads();
    int gid = blockIdx.x * 1024 + threadIdx.x;
    if (gid <= N) {
        int rp = d_cur[gid] + off_sh;
        d_rp[gid] = rp;
        d_cur[gid] = rp;                           // fill cursor
        if (gid < N) {
            int c = d_cnt[gid];
            int end = rp + ((c + 7) & ~7);
            for (int p = rp + c; p < end; p++) d_csr[p] = N;   // sentinel tail
        }
    }
}

// ---------------- CSR fill -------------------------------------------------
__global__ void fill_k(int E) {
    int e = blockIdx.x * blockDim.x + threadIdx.x;
    if (e >= E) return;
    int d = d_dst32[e];
    int pos = atomicAdd(&d_cur[d], 1);
    d_csr[pos] = d_src32[e];
}

// ---------------- GEMM1 (raw): g1 = x @ W1 (aux stream) --------------------
__global__ void gemm1_raw(const float* __restrict__ x, const float* __restrict__ W1, int N) {
    __shared__ float Ws[IN_DIM * HID];
    for (int i = threadIdx.x; i < IN_DIM * HID; i += blockDim.x) Ws[i] = W1[i];
    __syncthreads();
    int r = blockIdx.x * blockDim.x + threadIdx.x;
    if (r >= N) return;

    float acc[HID];
#pragma unroll
    for (int c = 0; c < HID; c++) acc[c] = 0.f;

    const float4* x4 = reinterpret_cast<const float4*>(x + (size_t)r * IN_DIM);
#pragma unroll 4
    for (int k4 = 0; k4 < IN_DIM / 4; k4++) {
        float4 xv = x4[k4];
        int k = k4 * 4;
#pragma unroll
        for (int c = 0; c < HID; c++) {
            acc[c] += xv.x * Ws[(k + 0) * HID + c]
                    + xv.y * Ws[(k + 1) * HID + c]
                    + xv.z * Ws[(k + 2) * HID + c]
                    + xv.w * Ws[(k + 3) * HID + c];
        }
    }
    float* out = d_g1 + (size_t)r * CP;
#pragma unroll
    for (int c = 0; c < HID; c++) out[c] = acc[c];
}

// ---------------- scale g1 by dinv (join point) ----------------------------
__global__ void scaleg1(int N) {
    int i = blockIdx.x * blockDim.x + threadIdx.x;
    int n4 = N * CP / 4;
    if (i >= n4) return;
    float s = d_dinv[i >> 3];
    float4* p = reinterpret_cast<float4*>(d_g1) + i;
    float4 v = *p;
    v.x *= s; v.y *= s; v.z *= s; v.w *= s;
    *p = v;
}

// ---- gather layer1 (float4 quads: 8 edges / 2 LDG.128) + fused GEMM2 ------
__global__ void __launch_bounds__(256) gather1(const float* __restrict__ b1,
                                               const float* __restrict__ W2, int N) {
    __shared__ float Ws[HID * CP];
    for (int i = threadIdx.x; i < HID * CP; i += blockDim.x) {
        int k = i / CP, c = i % CP;
        Ws[i] = (c < NCLS) ? W2[k * NCLS + c] : 0.f;
    }
    __syncthreads();

    int tid  = threadIdx.x;
    int lane = tid & 31;
    int q    = lane & 7;          // feature quad 0..7
    int eg   = lane >> 3;         // edge group 0..3
    int warp = (blockIdx.x * blockDim.x + tid) >> 5;
    int nwarps = (gridDim.x * blockDim.x) >> 5;
    float4 bv4 = reinterpret_cast<const float4*>(b1)[q];

    for (int v = warp; v < N; v += nwarps) {
        int beg = d_rp[v];
        int nb  = (d_rp[v + 1] - beg) >> 3;          // blocks of 8 edges
        const int4* ip = reinterpret_cast<const int4*>(d_csr + beg);
        float4 acc = make_float4(0.f, 0.f, 0.f, 0.f);
        int4 ia, ib;
        if (nb > 0) { ia = ip[0]; ib = ip[1]; }
        for (int b = 0; b < nb; b++) {
            int4 na, nbx;
            if (b + 1 < nb) { na = ip[2 * b + 2]; nbx = ip[2 * b + 3]; }
            int s0 = (eg == 0) ? ia.x : (eg == 1) ? ia.y : (eg == 2) ? ia.z : ia.w;
            int s1 = (eg == 0) ? ib.x : (eg == 1) ? ib.y : (eg == 2) ? ib.z : ib.w;
            float4 va = *reinterpret_cast<const float4*>(d_g1 + (size_t)s0 * CP + q * 4);
            float4 vb = *reinterpret_cast<const float4*>(d_g1 + (size_t)s1 * CP + q * 4);
            acc.x += va.x + vb.x; acc.y += va.y + vb.y;
            acc.z += va.z + vb.z; acc.w += va.w + vb.w;
            ia = na; ib = nbx;
        }
        // reduce across the 4 edge groups (lanes xor 8, 16)
#pragma unroll
        for (int o = 8; o <= 16; o <<= 1) {
            acc.x += __shfl_xor_sync(0xffffffffu, acc.x, o);
            acc.y += __shfl_xor_sync(0xffffffffu, acc.y, o);
            acc.z += __shfl_xor_sync(0xffffffffu, acc.z, o);
            acc.w += __shfl_xor_sync(0xffffffffu, acc.w, o);
        }
        float4 self = *reinterpret_cast<const float4*>(d_g1 + (size_t)v * CP + q * 4);
        float dv = d_dinv[v];
        float4 h;
        h.x = fmaxf(dv * (acc.x + self.x) + bv4.x, 0.f);
        h.y = fmaxf(dv * (acc.y + self.y) + bv4.y, 0.f);
        h.z = fmaxf(dv * (acc.z + self.z) + bv4.z, 0.f);
        h.w = fmaxf(dv * (acc.w + self.w) + bv4.w, 0.f);

        // fused GEMM2: g2[c] = dv * sum_k h[k] * W2[k][c], c = lane
        float g2c = 0.f;
#pragma unroll
        for (int q2 = 0; q2 < 8; q2++) {
            float hx = __shfl_sync(0xffffffffu, h.x, q2);
            float hy = __shfl_sync(0xffffffffu, h.y, q2);
            float hz = __shfl_sync(0xffffffffu, h.z, q2);
            float hw = __shfl_sync(0xffffffffu, h.w, q2);
            g2c += hx * Ws[(4 * q2 + 0) * CP + lane] + hy * Ws[(4 * q2 + 1) * CP + lane]
                 + hz * Ws[(4 * q2 + 2) * CP + lane] + hw * Ws[(4 * q2 + 3) * CP + lane];
        }
        d_g2[(size_t)v * CP + lane] = dv * g2c;
    }
}

// ---- gather layer2 (float4 quads) + softmax + FX + bf16 copy + NFX --------
__global__ void __launch_bounds__(256) gather2(const float* __restrict__ b2,
                                               float* __restrict__ fx_out, int N) {
    __shared__ float Ss[32];
    __shared__ float b2s[32];
    int tid  = threadIdx.x;
    int lane = tid & 31;
    if (tid < 32) { Ss[tid] = 0.f; b2s[tid] = (tid < NCLS) ? b2[tid] : 0.f; }
    __syncthreads();

    int q    = lane & 7;
    int eg   = lane >> 3;
    int warp = (blockIdx.x * blockDim.x + tid) >> 5;
    int nwarps = (gridDim.x * blockDim.x) >> 5;
    float4 bv4 = reinterpret_cast<const float4*>(b2s)[q];
    float4 ls4 = make_float4(0.f, 0.f, 0.f, 0.f);

    for (int v = warp; v < N; v += nwarps) {
        int beg = d_rp[v];
        int nb  = (d_rp[v + 1] - beg) >> 3;
        const int4* ip = reinterpret_cast<const int4*>(d_csr + beg);
        float4 acc = make_float4(0.f, 0.f, 0.f, 0.f);
        int4 ia, ib;
        if (nb > 0) { ia = ip[0]; ib = ip[1]; }
        for (int b = 0; b < nb; b++) {
            int4 na, nbx;
            if (b + 1 < nb) { na = ip[2 * b + 2]; nbx = ip[2 * b + 3]; }
            int s0 = (eg == 0) ? ia.x : (eg == 1) ? ia.y : (eg == 2) ? ia.z : ia.w;
            int s1 = (eg == 0) ? ib.x : (eg == 1) ? ib.y : (eg == 2) ? ib.z : ib.w;
            float4 va = *reinterpret_cast<const float4*>(d_g2 + (size_t)s0 * CP + q * 4);
            float4 vb = *reinterpret_cast<const float4*>(d_g2 + (size_t)s1 * CP + q * 4);
            acc.x += va.x + vb.x; acc.y += va.y + vb.y;
            acc.z += va.z + vb.z; acc.w += va.w + vb.w;
            ia = na; ib = nbx;
        }
#pragma unroll
        for (int o = 8; o <= 16; o <<= 1) {
            acc.x += __shfl_xor_sync(0xffffffffu, acc.x, o);
            acc.y += __shfl_xor_sync(0xffffffffu, acc.y, o);
            acc.z += __shfl_xor_sync(0xffffffffu, acc.z, o);
            acc.w += __shfl_xor_sync(0xffffffffu, acc.w, o);
        }
        float4 self = *reinterpret_cast<const float4*>(d_g2 + (size_t)v * CP + q * 4);
        float dv = d_dinv[v];
        float4 lg;
        lg.x = dv * (acc.x + self.x) + bv4.x;
        lg.y = dv * (acc.y + self.y) + bv4.y;
        lg.z = dv * (acc.z + self.z) + bv4.z;
        lg.w = dv * (acc.w + self.w) + bv4.w;
        if (q == 7) { lg.z = -1e30f; lg.w = -1e30f; }   // classes 30,31

        // softmax over 32 features: per-lane comps, then 8-lane group reduce
        float mx = fmaxf(fmaxf(lg.x, lg.y), fmaxf(lg.z, lg.w));
#pragma unroll
        for (int o = 1; o <= 4; o <<= 1) mx = fmaxf(mx, __shfl_xor_sync(0xffffffffu, mx, o));
        float4 ex;
        ex.x = expf(lg.x - mx); ex.y = expf(lg.y - mx);
        ex.z = expf(lg.z - mx); ex.w = expf(lg.w - mx);
        float sum = ex.x + ex.y + ex.z + ex.w;
#pragma unroll
        for (int o = 1; o <= 4; o <<= 1) sum += __shfl_xor_sync(0xffffffffu, sum, o);
        float inv = 1.f / sum;
        float4 fx;
        fx.x = ex.x * inv; fx.y = ex.y * inv; fx.z = ex.z * inv; fx.w = ex.w * inv;

        if (eg == 0) {
            // FX output (30 floats/row, float2 stores — 8B aligned)
            float* base = fx_out + (size_t)v * NCLS;
            *reinterpret_cast<float2*>(base + 4 * q) = make_float2(fx.x, fx.y);
            if (q < 7)
                *reinterpret_cast<float2*>(base + 4 * q + 2) = make_float2(fx.z, fx.w);
            // bf16 packed row for FF (fx.z/w at q7 are exactly 0)
            __nv_bfloat162 p0 = __floats2bfloat162_rn(fx.x, fx.y);
            __nv_bfloat162 p1 = __floats2bfloat162_rn(fx.z, fx.w);
            d_fx16[(size_t)v * 16 + 2 * q]     = p0;
            d_fx16[(size_t)v * 16 + 2 * q + 1] = p1;
        }
        // NFX partials (log1p(0)=0 for padded comps — safe)
        ls4.x += log1pf(-fx.x * fx.x);
        ls4.y += log1pf(-fx.y * fx.y);
        ls4.z += log1pf(-fx.z * fx.z);
        ls4.w += log1pf(-fx.w * fx.w);
    }
    if (eg == 0) {
        atomicAdd(&Ss[4 * q + 0], ls4.x);
        atomicAdd(&Ss[4 * q + 1], ls4.y);
        atomicAdd(&Ss[4 * q + 2], ls4.z);
        atomicAdd(&Ss[4 * q + 3], ls4.w);
    }
    __syncthreads();
    if (tid < NCLS) d_partialS[tid * gridDim.x + blockIdx.x] = Ss[tid];
}

// ---------------- FF + MSE partials (2 edges per 4-lane group) -------------
__global__ void ff_k(const float* __restrict__ ep, int E) {
    __shared__ float sAcc;
    int tid = threadIdx.x;
    if (tid == 0) sAcc = 0.f;
    __syncthreads();

    int idx = blockIdx.x * blockDim.x + tid;
    int grp = idx >> 2, c = idx & 3;
    int e0 = grp * 2;
    int nGrp = (E + 1) >> 1;
    bool v0 = (grp < nGrp) && (e0 < E);
    bool v1 = (grp < nGrp) && (e0 + 1 < E);

    float p0 = 0.f, p1 = 0.f;
    if (v0) {
        int s0 = d_src32[e0], dd0 = d_dst32[e0];
        uint4 A0 = reinterpret_cast<const uint4*>(d_fx16 + (size_t)s0  * 16)[c];
        uint4 B0 = reinterpret_cast<const uint4*>(d_fx16 + (size_t)dd0 * 16)[c];
        const unsigned int aw[4] = {A0.x, A0.y, A0.z, A0.w};
        const unsigned int bw[4] = {B0.x, B0.y, B0.z, B0.w};
#pragma unroll
        for (int j = 0; j < 4; j++) {
            float2 af = __bfloat1622float2(*reinterpret_cast<const __nv_bfloat162*>(&aw[j]));
            float2 bf = __bfloat1622float2(*reinterpret_cast<const __nv_bfloat162*>(&bw[j]));
            p0 += af.x * bf.x + af.y * bf.y;
        }
    }
    if (v1) {
        int s1 = d_src32[e0 + 1], dd1 = d_dst32[e0 + 1];
        uint4 A1 = reinterpret_cast<const uint4*>(d_fx16 + (size_t)s1  * 16)[c];
        uint4 B1 = reinterpret_cast<const uint4*>(d_fx16 + (size_t)dd1 * 16)[c];
        const unsigned int aw[4] = {A1.x, A1.y, A1.z, A1.w};
        const unsigned int bw[4] = {B1.x, B1.y, B1.z, B1.w};
#pragma unroll
        for (int j = 0; j < 4; j++) {
            float2 af = __bfloat1622float2(*reinterpret_cast<const __nv_bfloat162*>(&aw[j]));
            float2 bf = __bfloat1622float2(*reinterpret_cast<const __nv_bfloat162*>(&bw[j]));
            p1 += af.x * bf.x + af.y * bf.y;
        }
    }

    p0 += __shfl_down_sync(0xffffffffu, p0, 1);
    p0 += __shfl_down_sync(0xffffffffu, p0, 2);
    p1 += __shfl_down_sync(0xffffffffu, p1, 1);
    p1 += __shfl_down_sync(0xffffffffu, p1, 2);

    float d2 = 0.f;
    if (c == 0) {
        if (v0) { float f = p0 - ep[e0];     d2 += f * f; }
        if (v1) { float f = p1 - ep[e0 + 1]; d2 += f * f; }
    }
    d2 += __shfl_down_sync(0xffffffffu, d2, 4);
    d2 += __shfl_down_sync(0xffffffffu, d2, 8);
    d2 += __shfl_down_sync(0xffffffffu, d2, 16);
    if ((tid & 31) == 0) atomicAdd(&sAcc, d2);
    __syncthreads();
    if (tid == 0) d_partialM[blockIdx.x] = sAcc;
}

// ---------------- finalize loss -------------------------------------------
__global__ void fin_k(float* __restrict__ out, int N, int E, int out_size, int nb_m) {
    __shared__ double sS[32];
    __shared__ double red[32];
    int tid = threadIdx.x, w = tid >> 5, lane = tid & 31;

    if (w < NCLS) {
        float s = 0.f;
        for (int k = lane; k < G2MAX; k += 32) s += d_partialS[w * G2MAX + k];
#pragma unroll
        for (int o = 16; o; o >>= 1) s += __shfl_down_sync(0xffffffffu, s, o);
        if (lane == 0) sS[w] = (double)s;
    }

    double m = 0.0;
    for (int k = tid; k < nb_m; k += 1024) m += (double)d_partialM[k];
#pragma unroll
    for (int o = 16; o; o >>= 1) m += __shfl_down_sync(0xffffffffu, m, o);
    if (lane == 0) red[w] = m;
    __syncthreads();

    if (tid == 0) {
        double mm = 0.0;
        for (int i = 0; i < 32; i++) mm += red[i];
        double preg = 0.0;
        for (int c = 0; c < NCLS; c++)
            preg -= log(1.0001 - exp(sS[c]));
        double loss = mm / (double)E + REG_C * preg;
        if (out_size > N * NCLS) out[(size_t)N * NCLS] = (float)loss;
    }
}

// ---------------- launch ---------------------------------------------------
extern "C" void kernel_launch(void* const* d_in, const int* in_sizes, int n_in,
                              void* d_out, int out_size) {
    const float* x   = (const float*)d_in[0];
    const void*  ei  = d_in[1];
    const float* ep  = (const float*)d_in[2];
    const float* W1  = (const float*)d_in[3];
    const float* b1  = (const float*)d_in[4];
    const float* W2  = (const float*)d_in[5];
    const float* b2  = (const float*)d_in[6];
    float* out = (float*)d_out;

    int N = in_sizes[0] / IN_DIM;    // 100000
    int E = in_sizes[2];             // 3200000
    int nb_scan = (N + 1 + 1023) / 1024;
    long long ff_threads = ((long long)E + 1) / 2 * 4;
    int nb_ff   = (int)((ff_threads + 1023) / 1024);
    int n4 = N * CP / 4;

    static cudaStream_t s_aux = nullptr;
    static cudaEvent_t ev_root = nullptr, ev_scan1 = nullptr, ev_g1 = nullptr;
    if (s_aux == nullptr) {
        cudaStreamCreateWithFlags(&s_aux, cudaStreamNonBlocking);
        cudaEventCreateWithFlags(&ev_root, cudaEventDisableTiming);
        cudaEventCreateWithFlags(&ev_scan1, cudaEventDisableTiming);
        cudaEventCreateWithFlags(&ev_g1,   cudaEventDisableTiming);
    }

    const int T = 256;

    // fork: aux stream runs gemm1_raw concurrently with CSR build
    cudaEventRecord(ev_root, 0);
    cudaStreamWaitEvent(s_aux, ev_root, 0);
    gemm1_raw<<<(N + 127) / 128, 128, 0, s_aux>>>(x, W1, N);

    // main chain: CSR build
    init_k       <<<(N + 1 + T - 1) / T, T>>>((const unsigned int*)ei, N);
    count_convert<<<(E + T - 1) / T, T>>>(ei, E);
    scan1        <<<nb_scan, 1024>>>(N);
    cudaEventRecord(ev_scan1, 0);

    cudaStreamWaitEvent(s_aux, ev_scan1, 0);
    scaleg1<<<(n4 + T - 1) / T, T, 0, s_aux>>>(N);
    cudaEventRecord(ev_g1, s_aux);

    scan3        <<<nb_scan, 1024>>>(N);
    fill_k       <<<(E + T - 1) / T, T>>>(E);

    cudaStreamWaitEvent(0, ev_g1, 0);
    gather1      <<<2048, 256>>>(b1, W2, N);
    gather2      <<<G2MAX, 256>>>(b2, out, N);
    ff_k         <<<nb_ff, 1024>>>(ep, E);
    fin_k        <<<1, 1024>>>(out, N, E, out_size, nb_ff);
}